// round 7
// baseline (speedup 1.0000x reference)
#include <cuda_runtime.h>
#include <cstdint>

#define B_CONST 8192
#define D_CONST 4096
#define MARGIN 0.5f
#define THREADS 256

#define ROW_BYTES (D_CONST * 4)          // 16384
#define HALF_BYTES (ROW_BYTES / 2)       // 8192
#define HALF_F4 (HALF_BYTES / 16)        // 512 float4 per row-half
// smem: [0,8) mbarA, [8,16) mbarB, [64, 64+48K) three row buffers
#define SMEM_BUF_OFF 64
#define SMEM_BYTES (SMEM_BUF_OFF + 3 * ROW_BYTES)

__global__ void zero_out_kernel(float* out) {
    out[0] = 0.0f;
}

__device__ __forceinline__ uint32_t smem_u32(const void* p) {
    uint32_t a;
    asm("{ .reg .u64 t; cvta.to.shared.u64 t, %1; cvt.u32.u64 %0, t; }"
        : "=r"(a) : "l"(p));
    return a;
}

__device__ __forceinline__ void mbar_init(uint32_t mbar, uint32_t count) {
    asm volatile("mbarrier.init.shared.b64 [%0], %1;" :: "r"(mbar), "r"(count) : "memory");
}

__device__ __forceinline__ void mbar_expect_tx(uint32_t mbar, uint32_t bytes) {
    asm volatile("mbarrier.arrive.expect_tx.shared.b64 _, [%0], %1;"
                 :: "r"(mbar), "r"(bytes) : "memory");
}

__device__ __forceinline__ void bulk_g2s(uint32_t dst_smem, const void* src_gmem,
                                         uint32_t bytes, uint32_t mbar) {
    asm volatile(
        "cp.async.bulk.shared::cta.global.mbarrier::complete_tx::bytes "
        "[%0], [%1], %2, [%3];"
        :: "r"(dst_smem), "l"(src_gmem), "r"(bytes), "r"(mbar) : "memory");
}

__device__ __forceinline__ void mbar_wait(uint32_t mbar, uint32_t parity) {
    asm volatile(
        "{\n\t"
        ".reg .pred P;\n\t"
        "W%=:\n\t"
        "mbarrier.try_wait.parity.acquire.cta.shared::cta.b64 P, [%0], %1, 0x989680;\n\t"
        "@P bra D%=;\n\t"
        "bra W%=;\n\t"
        "D%=:\n\t"
        "}"
        :: "r"(mbar), "r"(parity) : "memory");
}

__global__ __launch_bounds__(THREADS) void triplet_loss_kernel(
    const float* __restrict__ feats,
    const float* __restrict__ label,
    const int* __restrict__ idx1,
    const int* __restrict__ idx2,
    float* __restrict__ out)
{
    extern __shared__ char smem[];
    const uint32_t smem_base = smem_u32(smem);
    const uint32_t mbarA = smem_base;
    const uint32_t mbarB = smem_base + 8;

    const int b = blockIdx.x;
    const int tid = threadIdx.x;

    const int i1 = idx1[b];
    const int i2 = idx2[b];

    const float* ga  = feats + (long long)b  * D_CONST;
    const float* g1  = feats + (long long)i1 * D_CONST;
    const float* g2  = feats + (long long)i2 * D_CONST;

    if (tid == 0) {
        mbar_init(mbarA, 1);
        mbar_init(mbarB, 1);
    }
    __syncthreads();

    if (tid == 0) {
        // Stage A: first halves of all three rows
        mbar_expect_tx(mbarA, 3 * HALF_BYTES);
        bulk_g2s(smem_base + SMEM_BUF_OFF + 0 * ROW_BYTES,             ga, HALF_BYTES, mbarA);
        bulk_g2s(smem_base + SMEM_BUF_OFF + 1 * ROW_BYTES,             g1, HALF_BYTES, mbarA);
        bulk_g2s(smem_base + SMEM_BUF_OFF + 2 * ROW_BYTES,             g2, HALF_BYTES, mbarA);
        // Stage B: second halves
        mbar_expect_tx(mbarB, 3 * HALF_BYTES);
        bulk_g2s(smem_base + SMEM_BUF_OFF + 0 * ROW_BYTES + HALF_BYTES, ga + D_CONST / 2, HALF_BYTES, mbarB);
        bulk_g2s(smem_base + SMEM_BUF_OFF + 1 * ROW_BYTES + HALF_BYTES, g1 + D_CONST / 2, HALF_BYTES, mbarB);
        bulk_g2s(smem_base + SMEM_BUF_OFF + 2 * ROW_BYTES + HALF_BYTES, g2 + D_CONST / 2, HALF_BYTES, mbarB);
    }

    const float4* sa = (const float4*)(smem + SMEM_BUF_OFF + 0 * ROW_BYTES);
    const float4* s1 = (const float4*)(smem + SMEM_BUF_OFF + 1 * ROW_BYTES);
    const float4* s2 = (const float4*)(smem + SMEM_BUF_OFF + 2 * ROW_BYTES);

    float s_abs1 = 0.f, s_abs2 = 0.f, s_sq1 = 0.f, s_sq2 = 0.f;

    #pragma unroll
    for (int h = 0; h < 2; h++) {
        mbar_wait(h == 0 ? mbarA : mbarB, 0);
        #pragma unroll
        for (int k = 0; k < HALF_F4 / THREADS; k++) {   // 2 iterations
            const int i = h * HALF_F4 + k * THREADS + tid;
            float4 av = sa[i];
            float4 v1 = s1[i];
            float4 v2 = s2[i];
            float d;
            d = av.x - v1.x; s_abs1 += fabsf(d); s_sq1 = fmaf(d, d, s_sq1);
            d = av.y - v1.y; s_abs1 += fabsf(d); s_sq1 = fmaf(d, d, s_sq1);
            d = av.z - v1.z; s_abs1 += fabsf(d); s_sq1 = fmaf(d, d, s_sq1);
            d = av.w - v1.w; s_abs1 += fabsf(d); s_sq1 = fmaf(d, d, s_sq1);
            d = av.x - v2.x; s_abs2 += fabsf(d); s_sq2 = fmaf(d, d, s_sq2);
            d = av.y - v2.y; s_abs2 += fabsf(d); s_sq2 = fmaf(d, d, s_sq2);
            d = av.z - v2.z; s_abs2 += fabsf(d); s_sq2 = fmaf(d, d, s_sq2);
            d = av.w - v2.w; s_abs2 += fabsf(d); s_sq2 = fmaf(d, d, s_sq2);
        }
    }

    // warp reduce
    #pragma unroll
    for (int off = 16; off > 0; off >>= 1) {
        s_abs1 += __shfl_down_sync(0xFFFFFFFF, s_abs1, off);
        s_abs2 += __shfl_down_sync(0xFFFFFFFF, s_abs2, off);
        s_sq1  += __shfl_down_sync(0xFFFFFFFF, s_sq1,  off);
        s_sq2  += __shfl_down_sync(0xFFFFFFFF, s_sq2,  off);
    }

    __shared__ float4 warp_sums[THREADS / 32];
    const int wid = tid >> 5;
    const int lid = tid & 31;
    if (lid == 0) warp_sums[wid] = make_float4(s_abs1, s_abs2, s_sq1, s_sq2);
    __syncthreads();

    if (wid == 0) {
        float4 v = (lid < THREADS / 32) ? warp_sums[lid]
                                        : make_float4(0.f, 0.f, 0.f, 0.f);
        #pragma unroll
        for (int off = (THREADS / 64); off > 0; off >>= 1) {
            v.x += __shfl_down_sync(0xFFFFFFFF, v.x, off);
            v.y += __shfl_down_sync(0xFFFFFFFF, v.y, off);
            v.z += __shfl_down_sync(0xFFFFFFFF, v.z, off);
            v.w += __shfl_down_sync(0xFFFFFFFF, v.w, off);
        }
        if (lid == 0) {
            const float l1_1 = v.x, l1_2 = v.y, sse1 = v.z, sse2 = v.w;
            const bool swap = (l1_1 >= l1_2);
            const float near_sse = swap ? sse2 : sse1;
            const float far_sse  = swap ? sse1 : sse2;
            const float la = label[b];
            const float l1 = label[i1];
            const float l2 = label[i2];
            const float near_label = swap ? l2 : l1;
            const float far_label  = swap ? l1 : l2;
            const float dfar  = la - far_label;
            const float dnear = la - near_label;
            const float alpha = dfar * dfar - dnear * dnear;
            const float loss = near_sse - far_sse + alpha * MARGIN;
            if (loss > 0.0f) atomicAdd(out, loss);
        }
    }
}

extern "C" void kernel_launch(void* const* d_in, const int* in_sizes, int n_in,
                              void* d_out, int out_size) {
    const float* feats = (const float*)d_in[0];
    const float* label = (const float*)d_in[1];
    const int*   idx1  = (const int*)d_in[2];
    const int*   idx2  = (const int*)d_in[3];
    float* out = (float*)d_out;

    static bool attr_set = false;
    if (!attr_set) {
        cudaFuncSetAttribute(triplet_loss_kernel,
                             cudaFuncAttributeMaxDynamicSharedMemorySize, SMEM_BYTES);
        attr_set = true;
    }

    zero_out_kernel<<<1, 1>>>(out);
    triplet_loss_kernel<<<B_CONST, THREADS, SMEM_BYTES>>>(feats, label, idx1, idx2, out);
}

// round 8
// speedup vs baseline: 1.1624x; 1.1624x over previous
#include <cuda_runtime.h>
#include <cstdint>

#define B_CONST 8192
#define D_CONST 4096
#define MARGIN 0.5f
#define THREADS 256

#define STAGE_F4 256                 // float4s per stream per stage (= THREADS)
#define NSTAGE   (D_CONST / 4 / STAGE_F4)   // 4 stages per row
#define DEPTH    2

__global__ void zero_out_kernel(float* out) {
    out[0] = 0.0f;
}

__device__ __forceinline__ uint32_t smem_u32(const void* p) {
    uint32_t a;
    asm("{ .reg .u64 t; cvta.to.shared.u64 t, %1; cvt.u32.u64 %0, t; }"
        : "=r"(a) : "l"(p));
    return a;
}

__device__ __forceinline__ void cp_async16(uint32_t dst_smem, const void* src) {
    asm volatile("cp.async.cg.shared.global [%0], [%1], 16;"
                 :: "r"(dst_smem), "l"(src) : "memory");
}

__device__ __forceinline__ void cp_commit() {
    asm volatile("cp.async.commit_group;" ::: "memory");
}

template <int N>
__device__ __forceinline__ void cp_wait() {
    asm volatile("cp.async.wait_group %0;" :: "n"(N) : "memory");
}

__global__ __launch_bounds__(THREADS) void triplet_loss_kernel(
    const float* __restrict__ feats,
    const float* __restrict__ label,
    const int* __restrict__ idx1,
    const int* __restrict__ idx2,
    float* __restrict__ out)
{
    // buf[depth][stream][STAGE_F4] float4s = 2*3*4KB = 24KB
    __shared__ float4 buf[DEPTH][3][STAGE_F4];

    const int b = blockIdx.x;
    const int tid = threadIdx.x;

    const int i1 = idx1[b];
    const int i2 = idx2[b];

    const float4* ga = (const float4*)(feats + (long long)b  * D_CONST);
    const float4* g1 = (const float4*)(feats + (long long)i1 * D_CONST);
    const float4* g2 = (const float4*)(feats + (long long)i2 * D_CONST);

    // Per-thread smem slots (self-consumption: each thread computes exactly
    // the elements it copied, so cp.async.wait_group is the only sync needed).
    const uint32_t s_a0 = smem_u32(&buf[0][0][tid]);
    const uint32_t s_10 = smem_u32(&buf[0][1][tid]);
    const uint32_t s_20 = smem_u32(&buf[0][2][tid]);
    const uint32_t s_a1 = smem_u32(&buf[1][0][tid]);
    const uint32_t s_11 = smem_u32(&buf[1][1][tid]);
    const uint32_t s_21 = smem_u32(&buf[1][2][tid]);

    float s_abs1 = 0.f, s_abs2 = 0.f, s_sq1 = 0.f, s_sq2 = 0.f;

    // Prologue: stage 0
    {
        const int idx = tid;
        cp_async16(s_a0, ga + idx);
        cp_async16(s_10, g1 + idx);
        cp_async16(s_20, g2 + idx);
        cp_commit();
    }

    #pragma unroll
    for (int s = 0; s < NSTAGE; s++) {
        if (s + 1 < NSTAGE) {
            const int idx = (s + 1) * STAGE_F4 + tid;
            const bool odd = (s + 1) & 1;
            cp_async16(odd ? s_a1 : s_a0, ga + idx);
            cp_async16(odd ? s_11 : s_10, g1 + idx);
            cp_async16(odd ? s_21 : s_20, g2 + idx);
            cp_commit();
            cp_wait<1>();   // stage s complete, stage s+1 in flight
        } else {
            cp_wait<0>();   // last stage complete
        }

        const int d = s & 1;
        float4 av = buf[d][0][tid];
        float4 v1 = buf[d][1][tid];
        float4 v2 = buf[d][2][tid];

        float dd;
        dd = av.x - v1.x; s_abs1 += fabsf(dd); s_sq1 = fmaf(dd, dd, s_sq1);
        dd = av.y - v1.y; s_abs1 += fabsf(dd); s_sq1 = fmaf(dd, dd, s_sq1);
        dd = av.z - v1.z; s_abs1 += fabsf(dd); s_sq1 = fmaf(dd, dd, s_sq1);
        dd = av.w - v1.w; s_abs1 += fabsf(dd); s_sq1 = fmaf(dd, dd, s_sq1);
        dd = av.x - v2.x; s_abs2 += fabsf(dd); s_sq2 = fmaf(dd, dd, s_sq2);
        dd = av.y - v2.y; s_abs2 += fabsf(dd); s_sq2 = fmaf(dd, dd, s_sq2);
        dd = av.z - v2.z; s_abs2 += fabsf(dd); s_sq2 = fmaf(dd, dd, s_sq2);
        dd = av.w - v2.w; s_abs2 += fabsf(dd); s_sq2 = fmaf(dd, dd, s_sq2);
    }

    // warp reduce
    #pragma unroll
    for (int off = 16; off > 0; off >>= 1) {
        s_abs1 += __shfl_down_sync(0xFFFFFFFF, s_abs1, off);
        s_abs2 += __shfl_down_sync(0xFFFFFFFF, s_abs2, off);
        s_sq1  += __shfl_down_sync(0xFFFFFFFF, s_sq1,  off);
        s_sq2  += __shfl_down_sync(0xFFFFFFFF, s_sq2,  off);
    }

    __shared__ float4 warp_sums[THREADS / 32];
    const int wid = tid >> 5;
    const int lid = tid & 31;
    if (lid == 0) warp_sums[wid] = make_float4(s_abs1, s_abs2, s_sq1, s_sq2);
    __syncthreads();

    if (wid == 0) {
        float4 v = (lid < THREADS / 32) ? warp_sums[lid]
                                        : make_float4(0.f, 0.f, 0.f, 0.f);
        #pragma unroll
        for (int off = (THREADS / 64); off > 0; off >>= 1) {
            v.x += __shfl_down_sync(0xFFFFFFFF, v.x, off);
            v.y += __shfl_down_sync(0xFFFFFFFF, v.y, off);
            v.z += __shfl_down_sync(0xFFFFFFFF, v.z, off);
            v.w += __shfl_down_sync(0xFFFFFFFF, v.w, off);
        }
        if (lid == 0) {
            const float l1_1 = v.x, l1_2 = v.y, sse1 = v.z, sse2 = v.w;
            const bool swap = (l1_1 >= l1_2);
            const float near_sse = swap ? sse2 : sse1;
            const float far_sse  = swap ? sse1 : sse2;
            const float la = label[b];
            const float l1 = label[i1];
            const float l2 = label[i2];
            const float near_label = swap ? l2 : l1;
            const float far_label  = swap ? l1 : l2;
            const float dfar  = la - far_label;
            const float dnear = la - near_label;
            const float alpha = dfar * dfar - dnear * dnear;
            const float loss = near_sse - far_sse + alpha * MARGIN;
            if (loss > 0.0f) atomicAdd(out, loss);
        }
    }
}

extern "C" void kernel_launch(void* const* d_in, const int* in_sizes, int n_in,
                              void* d_out, int out_size) {
    const float* feats = (const float*)d_in[0];
    const float* label = (const float*)d_in[1];
    const int*   idx1  = (const int*)d_in[2];
    const int*   idx2  = (const int*)d_in[3];
    float* out = (float*)d_out;

    zero_out_kernel<<<1, 1>>>(out);
    triplet_loss_kernel<<<B_CONST, THREADS>>>(feats, label, idx1, idx2, out);
}